// round 13
// baseline (speedup 1.0000x reference)
#include <cuda_runtime.h>
#include <cstdint>

#define SEQ   4096
#define DIM   64
#define NBH   16          // B*H
#define QB    64
#define KB    64
#define NT    (SEQ/KB)    // 64 key tiles
#define MW    (SEQ/32)    // packed mask words per row
// scale * log2(e): scores computed directly in log2 domain for ex2.approx
#define SCALE_L2E 0.1803368801111204f

#define KRS 80            // K row stride (floats): LDS.128 conflict-free layout
#define VRS 64            // V smem row stride (floats): swizzled, no pad

// Scratch (allocation-free per harness rules).
__device__ unsigned g_pmask[SEQ * MW];
__device__ float g_Kr[NBH * SEQ * KRS];   // rna tf32, packed for LDS.128 b-frags
__device__ float g_Vr[NBH * SEQ * DIM];   // rna tf32, col-permuted + XOR chunk swizzle
__device__ float g_inv[NBH * SEQ];        // 1 / rowsum

__device__ __forceinline__ unsigned f2tf32(float f) {
    unsigned u;
    asm("cvt.rna.tf32.f32 %0, %1;" : "=r"(u) : "f"(f));
    return u;
}
__device__ __forceinline__ float tf32f(float f) { return __uint_as_float(f2tf32(f)); }

__device__ __forceinline__ float ex2(float x) {
    float y;
    asm("ex2.approx.f32 %0, %1;" : "=f"(y) : "f"(x));
    return y;
}

__device__ __forceinline__ void mma_tf32(float c[4], const unsigned a[4],
                                         unsigned b0, unsigned b1) {
    asm volatile(
        "mma.sync.aligned.m16n8k8.row.col.f32.tf32.tf32.f32 "
        "{%0,%1,%2,%3}, {%4,%5,%6,%7}, {%8,%9}, {%0,%1,%2,%3};\n"
        : "+f"(c[0]), "+f"(c[1]), "+f"(c[2]), "+f"(c[3])
        : "r"(a[0]), "r"(a[1]), "r"(a[2]), "r"(a[3]), "r"(b0), "r"(b1));
}

__device__ __forceinline__ void cp_async16(void* dst, const void* src) {
    unsigned s = (unsigned)__cvta_generic_to_shared(dst);
    asm volatile("cp.async.cg.shared.global [%0], [%1], 16;\n" :: "r"(s), "l"(src));
}
#define CP_COMMIT() asm volatile("cp.async.commit_group;\n")
#define CP_WAIT0()  asm volatile("cp.async.wait_group 0;\n")

// ===========================================================================
// Prep kernels
// ===========================================================================
__global__ __launch_bounds__(256) void pack_mask_kernel(const int* __restrict__ mask) {
    int g = blockIdx.x * 256 + threadIdx.x;
    unsigned b = __ballot_sync(0xffffffffu, mask[g] != 0);
    if ((threadIdx.x & 31) == 0) g_pmask[g >> 5] = b;
}

// K v2: rna round + pack at position  lc*20 + ds*2 + h  <-  K[ds*8 + lc + 4h]
// (4 pad floats per lc-group of 20; row stride 80).
__global__ __launch_bounds__(256) void prep_k_kernel(const float* __restrict__ K) {
    int o = blockIdx.x * 256 + threadIdx.x;          // output element index
    int p = o % KRS;
    int row = o / KRS;
    int lcq = p / 20, q = p % 20;
    float val = 0.f;
    if (q < 16) {
        int ds = q >> 1, h = q & 1;
        val = tf32f(K[row * DIM + ds * 8 + lcq + 4 * h]);
    }
    g_Kr[o] = val;
}

// V: rna round + col permutation (vt*8+gr -> gr*8+vt) + XOR chunk swizzle.
// key(r) = ((r>>1)&1) | (((r>>2)&1)<<2)  -> rows {2lc, 2lc+1} share key
// gsw(lc) in {0,1,4,5}; every LDS.128 phase conflict-free for the AV row
// indexing (rows nt*8+2lc, nt*8+2lc+1).
__global__ __launch_bounds__(256) void prep_v_kernel(const float* __restrict__ V) {
    int o = blockIdx.x * 256 + threadIdx.x;
    int p = o & (DIM - 1);
    int row = (o >> 6);                               // global row index
    int key = ((row >> 1) & 1) | (((row >> 2) & 1) << 2);
    int chunkp = p >> 2, within = p & 3;
    int chunk = chunkp ^ key;                         // logical chunk
    int f = chunk * 4 + within;                       // logical permuted col
    int gr = f >> 3, vt = f & 7;
    int c_in = vt * 8 + gr;
    g_Vr[o] = tf32f(V[(o - p) + c_in]);
}

// ===========================================================================
// Kernel A: row sums of exp(masked scores). K-smem only -> low regs, high occ.
// ===========================================================================
__global__ __launch_bounds__(128) void rowsum_kernel(
    const float* __restrict__ Q, float* __restrict__ dummy)
{
    const int bh = blockIdx.y;
    const int q0 = blockIdx.x * QB;
    const float* Qp = Q + ((size_t)bh * SEQ + q0) * DIM;
    const float* Kp = g_Kr + (size_t)bh * SEQ * KRS;

    extern __shared__ float smemA[];
    float (*Ks)[KB][KRS] = reinterpret_cast<float (*)[KB][KRS]>(smemA);

    const int tid  = threadIdx.x;
    const int warp = tid >> 5;
    const int lane = tid & 31;
    const int gr   = lane >> 2;
    const int lc   = lane & 3;
    const int qg0  = q0 + warp * 16 + gr;
    const unsigned* pmBase = g_pmask + (size_t)qg0 * MW;

    // Stage Q into Ks[0] (plain layout, row stride KRS); hoist A fragments.
#pragma unroll
    for (int it = 0; it < 8; it++) {
        int j = tid + it * 128;
        int r = j >> 4, cc = (j & 15) << 2;
        float4 v = *reinterpret_cast<const float4*>(Qp + (size_t)r * DIM + cc);
        Ks[0][r][cc + 0] = tf32f(v.x * SCALE_L2E);
        Ks[0][r][cc + 1] = tf32f(v.y * SCALE_L2E);
        Ks[0][r][cc + 2] = tf32f(v.z * SCALE_L2E);
        Ks[0][r][cc + 3] = tf32f(v.w * SCALE_L2E);
    }
    __syncthreads();
    unsigned a[8][4];
#pragma unroll
    for (int ds = 0; ds < 8; ds++) {
        a[ds][0] = __float_as_uint(Ks[0][warp * 16 + gr    ][ds * 8 + lc    ]);
        a[ds][1] = __float_as_uint(Ks[0][warp * 16 + gr + 8][ds * 8 + lc    ]);
        a[ds][2] = __float_as_uint(Ks[0][warp * 16 + gr    ][ds * 8 + lc + 4]);
        a[ds][3] = __float_as_uint(Ks[0][warp * 16 + gr + 8][ds * 8 + lc + 4]);
    }
    __syncthreads();

    // thread t copies half a row: row t/2, 40 floats starting at (t&1)*40
    const int cr  = tid >> 1;
    const int cc0 = (tid & 1) * 40;
    auto issueK = [&](int kt, int buf) {
        const float* Kt = Kp + (size_t)kt * KB * KRS + (size_t)cr * KRS + cc0;
#pragma unroll
        for (int it = 0; it < 10; it++)
            cp_async16(&Ks[buf][cr][cc0 + it * 4], Kt + it * 4);
    };

    float rs0 = 0.f, rs1 = 0.f;
    issueK(0, 0); CP_COMMIT();

    for (int kt = 0; kt < NT; kt++) {
        const int cur = kt & 1;
        CP_WAIT0();
        __syncthreads();                        // single barrier per kt
        if (kt + 1 < NT) { issueK(kt + 1, cur ^ 1); CP_COMMIT(); }

        const unsigned* pm = pmBase + kt * 2;
        unsigned w0a = pm[0], w0b = pm[1];
        unsigned w1a = pm[8 * MW], w1b = pm[8 * MW + 1];

        float c[8][4];
#pragma unroll
        for (int nt = 0; nt < 8; nt++) { c[nt][0]=c[nt][1]=c[nt][2]=c[nt][3]=0.f; }
#pragma unroll
        for (int j = 0; j < 4; j++) {           // ds pairs (2j, 2j+1)
#pragma unroll
            for (int nt = 0; nt < 8; nt++) {
                float4 kc = *reinterpret_cast<const float4*>(
                    &Ks[cur][nt * 8 + gr][lc * 20 + j * 4]);
                mma_tf32(c[nt], a[2*j    ], __float_as_uint(kc.x), __float_as_uint(kc.y));
                mma_tf32(c[nt], a[2*j + 1], __float_as_uint(kc.z), __float_as_uint(kc.w));
            }
        }
#pragma unroll
        for (int nt = 0; nt < 8; nt++) {
            int colb = nt * 8 + lc * 2;
            unsigned wa = (nt < 4) ? w0a : w0b;
            unsigned wb = (nt < 4) ? w1a : w1b;
            int sh = colb & 31;
            float e0 = ((wa >> sh) & 1u)       ? ex2(c[nt][0]) : 0.f;
            float e1 = ((wa >> (sh + 1)) & 1u) ? ex2(c[nt][1]) : 0.f;
            float e2 = ((wb >> sh) & 1u)       ? ex2(c[nt][2]) : 0.f;
            float e3 = ((wb >> (sh + 1)) & 1u) ? ex2(c[nt][3]) : 0.f;
            rs0 += e0 + e1;
            rs1 += e2 + e3;
        }
    }

    rs0 += __shfl_xor_sync(0xffffffffu, rs0, 1);
    rs0 += __shfl_xor_sync(0xffffffffu, rs0, 2);
    rs1 += __shfl_xor_sync(0xffffffffu, rs1, 1);
    rs1 += __shfl_xor_sync(0xffffffffu, rs1, 2);
    if (lc == 0) {
        g_inv[bh * SEQ + qg0    ] = 1.f / rs0;
        g_inv[bh * SEQ + qg0 + 8] = 1.f / rs1;
    }
    (void)dummy;
}

// ===========================================================================
// Kernel B: recompute scores, write normalized P once, O = Pn @ V.
// Normalization folded into MMA accumulator init (log2 domain).
// ===========================================================================
__global__ __launch_bounds__(128) void av_kernel(
    const float* __restrict__ Q, float* __restrict__ P, float* __restrict__ O)
{
    const int bh = blockIdx.y;
    const int q0 = blockIdx.x * QB;
    const float* Qp = Q + ((size_t)bh * SEQ + q0) * DIM;
    const float* Kp = g_Kr + (size_t)bh * SEQ * KRS;
    const float* Vp = g_Vr + (size_t)bh * SEQ * DIM;
    float* Pp = P + ((size_t)bh * SEQ + q0) * SEQ;
    float* Op = O + ((size_t)bh * SEQ + q0) * DIM;

    extern __shared__ float smem[];
    float (*Ks)[KB][KRS] = reinterpret_cast<float (*)[KB][KRS]>(smem);
    float (*Vs)[KB][VRS] = reinterpret_cast<float (*)[KB][VRS]>(smem + 2 * KB * KRS);

    const int tid  = threadIdx.x;
    const int warp = tid >> 5;
    const int lane = tid & 31;
    const int gr   = lane >> 2;
    const int lc   = lane & 3;
    const int qg0  = q0 + warp * 16 + gr;
    const int gsw  = (lc & 1) | ((lc & 2) << 1);   // V chunk swizzle key for rows 2lc,2lc+1
    const unsigned* pmBase = g_pmask + (size_t)qg0 * MW;

    // normalization as log2-domain accumulator bias
    const float l0 = __log2f(g_inv[bh * SEQ + qg0    ]);
    const float l1 = __log2f(g_inv[bh * SEQ + qg0 + 8]);

    // Stage Q into Ks[0]; hoist A fragments.
#pragma unroll
    for (int it = 0; it < 8; it++) {
        int j = tid + it * 128;
        int r = j >> 4, cc = (j & 15) << 2;
        float4 v = *reinterpret_cast<const float4*>(Qp + (size_t)r * DIM + cc);
        Ks[0][r][cc + 0] = tf32f(v.x * SCALE_L2E);
        Ks[0][r][cc + 1] = tf32f(v.y * SCALE_L2E);
        Ks[0][r][cc + 2] = tf32f(v.z * SCALE_L2E);
        Ks[0][r][cc + 3] = tf32f(v.w * SCALE_L2E);
    }
    __syncthreads();
    unsigned a[8][4];
#pragma unroll
    for (int ds = 0; ds < 8; ds++) {
        a[ds][0] = __float_as_uint(Ks[0][warp * 16 + gr    ][ds * 8 + lc    ]);
        a[ds][1] = __float_as_uint(Ks[0][warp * 16 + gr + 8][ds * 8 + lc    ]);
        a[ds][2] = __float_as_uint(Ks[0][warp * 16 + gr    ][ds * 8 + lc + 4]);
        a[ds][3] = __float_as_uint(Ks[0][warp * 16 + gr + 8][ds * 8 + lc + 4]);
    }
    __syncthreads();

    const int cr  = tid >> 1;
    const int cc0 = (tid & 1) * 40;
    auto issueK = [&](int kt, int buf) {
        const float* Kt = Kp + (size_t)kt * KB * KRS + (size_t)cr * KRS + cc0;
#pragma unroll
        for (int it = 0; it < 10; it++)
            cp_async16(&Ks[buf][cr][cc0 + it * 4], Kt + it * 4);
    };
    auto issueV = [&](int kt, int buf) {
        const float* Vt = Vp + (size_t)kt * KB * DIM;
#pragma unroll
        for (int it = 0; it < 8; it++) {
            int j = tid + it * 128;
            int r = j >> 4, cc = (j & 15) << 2;
            cp_async16(&Vs[buf][r][cc], Vt + (size_t)r * DIM + cc);
        }
    };

    float acc[8][4];
#pragma unroll
    for (int vt = 0; vt < 8; vt++) { acc[vt][0]=acc[vt][1]=acc[vt][2]=acc[vt][3]=0.f; }

    issueK(0, 0); issueV(0, 0); CP_COMMIT();

    for (int kt = 0; kt < NT; kt++) {
        const int cur = kt & 1;
        CP_WAIT0();
        __syncthreads();                        // single barrier per kt
        if (kt + 1 < NT) { issueK(kt + 1, cur ^ 1); issueV(kt + 1, cur ^ 1); CP_COMMIT(); }

        const unsigned* pm = pmBase + kt * 2;
        unsigned w0a = pm[0], w0b = pm[1];
        unsigned w1a = pm[8 * MW], w1b = pm[8 * MW + 1];

        float c[8][4];
#pragma unroll
        for (int nt = 0; nt < 8; nt++) {
            c[nt][0] = l0; c[nt][1] = l0; c[nt][2] = l1; c[nt][3] = l1;
        }
#pragma unroll
        for (int j = 0; j < 4; j++) {
#pragma unroll
            for (int nt = 0; nt < 8; nt++) {
                float4 kc = *reinterpret_cast<const float4*>(
                    &Ks[cur][nt * 8 + gr][lc * 20 + j * 4]);
                mma_tf32(c[nt], a[2*j    ], __float_as_uint(kc.x), __float_as_uint(kc.y));
                mma_tf32(c[nt], a[2*j + 1], __float_as_uint(kc.z), __float_as_uint(kc.w));
            }
        }

#pragma unroll
        for (int nt = 0; nt < 8; nt++) {
            int colb = nt * 8 + lc * 2;
            unsigned wa = (nt < 4) ? w0a : w0b;
            unsigned wb = (nt < 4) ? w1a : w1b;
            int sh = colb & 31;
            float p0 = ((wa >> sh) & 1u)       ? ex2(c[nt][0]) : 0.f;
            float p1 = ((wa >> (sh + 1)) & 1u) ? ex2(c[nt][1]) : 0.f;
            float p2 = ((wb >> sh) & 1u)       ? ex2(c[nt][2]) : 0.f;
            float p3 = ((wb >> (sh + 1)) & 1u) ? ex2(c[nt][3]) : 0.f;

            // final attention store (normalized, streaming hint)
            int col = kt * KB + colb;
            __stcs(reinterpret_cast<float2*>(Pp + (size_t)(warp * 16 + gr    ) * SEQ + col),
                   make_float2(p0, p1));
            __stcs(reinterpret_cast<float2*>(Pp + (size_t)(warp * 16 + gr + 8) * SEQ + col),
                   make_float2(p2, p3));

            // C-fragment IS the A-fragment under the permuted-k AV mma.
            unsigned afr[4];
            afr[0] = f2tf32(p0);
            afr[1] = f2tf32(p2);
            afr[2] = f2tf32(p1);
            afr[3] = f2tf32(p3);

            // B operand rows permuted to match: b0 = V[2lc][*], b1 = V[2lc+1][*]
            const float* vrow0 = &Vs[cur][nt * 8 + 2 * lc    ][0];
            const float* vrow1 = &Vs[cur][nt * 8 + 2 * lc + 1][0];
            float4 A0 = *reinterpret_cast<const float4*>(vrow0 + (((2*gr  ) ^ gsw) << 2));
            float4 A1 = *reinterpret_cast<const float4*>(vrow0 + (((2*gr+1) ^ gsw) << 2));
            float4 B0 = *reinterpret_cast<const float4*>(vrow1 + (((2*gr  ) ^ gsw) << 2));
            float4 B1 = *reinterpret_cast<const float4*>(vrow1 + (((2*gr+1) ^ gsw) << 2));

            mma_tf32(acc[0], afr, __float_as_uint(A0.x), __float_as_uint(B0.x));
            mma_tf32(acc[1], afr, __float_as_uint(A0.y), __float_as_uint(B0.y));
            mma_tf32(acc[2], afr, __float_as_uint(A0.z), __float_as_uint(B0.z));
            mma_tf32(acc[3], afr, __float_as_uint(A0.w), __float_as_uint(B0.w));
            mma_tf32(acc[4], afr, __float_as_uint(A1.x), __float_as_uint(B1.x));
            mma_tf32(acc[5], afr, __float_as_uint(A1.y), __float_as_uint(B1.y));
            mma_tf32(acc[6], afr, __float_as_uint(A1.z), __float_as_uint(B1.z));
            mma_tf32(acc[7], afr, __float_as_uint(A1.w), __float_as_uint(B1.w));
        }
    }

    // Write O. acc[vt] holds output columns vt*8 + {2lc, 2lc+1} for rows gr, gr+8.
#pragma unroll
    for (int vt = 0; vt < 8; vt++) {
        int col = vt * 8 + lc * 2;
        *reinterpret_cast<float2*>(Op + (size_t)(warp * 16 + gr    ) * DIM + col) =
            make_float2(acc[vt][0], acc[vt][1]);
        *reinterpret_cast<float2*>(Op + (size_t)(warp * 16 + gr + 8) * DIM + col) =
            make_float2(acc[vt][2], acc[vt][3]);
    }
}

// ===========================================================================
extern "C" void kernel_launch(void* const* d_in, const int* in_sizes, int n_in,
                              void* d_out, int out_size) {
    (void)in_sizes; (void)n_in; (void)out_size;
    const float* Q   = (const float*)d_in[0];
    const float* K   = (const float*)d_in[1];
    const float* V   = (const float*)d_in[2];
    const int*  mask = (const int*)d_in[3];

    float* O = (float*)d_out;
    float* P = (float*)d_out + (size_t)NBH * SEQ * DIM;

    const int smemA = 2 * KB * KRS * sizeof(float);                       // 40960
    const int smemB = (2 * KB * KRS + 2 * KB * VRS) * sizeof(float);      // 73728
    cudaFuncSetAttribute(rowsum_kernel,
                         cudaFuncAttributeMaxDynamicSharedMemorySize, smemA);
    cudaFuncSetAttribute(av_kernel,
                         cudaFuncAttributeMaxDynamicSharedMemorySize, smemB);

    pack_mask_kernel<<<(SEQ * SEQ) / 256, 256>>>(mask);
    prep_k_kernel<<<(NBH * SEQ * KRS) / 256, 256>>>(K);
    prep_v_kernel<<<(NBH * SEQ * DIM) / 256, 256>>>(V);

    dim3 grid(SEQ / QB, NBH);
    rowsum_kernel<<<grid, 128, smemA>>>(Q, O);
    av_kernel<<<grid, 128, smemB>>>(Q, P, O);
}

// round 14
// speedup vs baseline: 1.4372x; 1.4372x over previous
#include <cuda_runtime.h>
#include <cstdint>

#define SEQ   4096
#define DIM   64
#define NBH   16          // B*H
#define QB    64
#define KB    64
#define NT    (SEQ/KB)    // 64 key tiles
#define MW    (SEQ/32)    // packed mask words per row
// scale * log2(e): scores computed directly in log2 domain for ex2.approx
#define SCALE_L2E 0.1803368801111204f

#define KRS 80            // K row stride (floats): LDS.128 packed b-frag layout
#define VRS 64            // V smem row stride (floats): swizzled, no pad

// Scratch (allocation-free per harness rules).
__device__ unsigned g_pmask[SEQ * MW];
__device__ float g_Kr[NBH * SEQ * KRS];   // rna tf32, packed for LDS.128 b-frags
__device__ float g_Vr[NBH * SEQ * DIM];   // rna tf32, col-permuted + XOR chunk swizzle
__device__ float g_inv[NBH * SEQ];        // 1 / rowsum

__device__ __forceinline__ unsigned f2tf32(float f) {
    unsigned u;
    asm("cvt.rna.tf32.f32 %0, %1;" : "=r"(u) : "f"(f));
    return u;
}
__device__ __forceinline__ float tf32f(float f) { return __uint_as_float(f2tf32(f)); }

__device__ __forceinline__ float ex2(float x) {
    float y;
    asm("ex2.approx.f32 %0, %1;" : "=f"(y) : "f"(x));
    return y;
}

__device__ __forceinline__ void mma_tf32(float c[4], const unsigned a[4],
                                         unsigned b0, unsigned b1) {
    asm volatile(
        "mma.sync.aligned.m16n8k8.row.col.f32.tf32.tf32.f32 "
        "{%0,%1,%2,%3}, {%4,%5,%6,%7}, {%8,%9}, {%0,%1,%2,%3};\n"
        : "+f"(c[0]), "+f"(c[1]), "+f"(c[2]), "+f"(c[3])
        : "r"(a[0]), "r"(a[1]), "r"(a[2]), "r"(a[3]), "r"(b0), "r"(b1));
}

__device__ __forceinline__ void cp_async16(void* dst, const void* src) {
    unsigned s = (unsigned)__cvta_generic_to_shared(dst);
    asm volatile("cp.async.cg.shared.global [%0], [%1], 16;\n" :: "r"(s), "l"(src));
}
#define CP_COMMIT() asm volatile("cp.async.commit_group;\n")

// ===========================================================================
// Prep kernels
// ===========================================================================
__global__ __launch_bounds__(256) void pack_mask_kernel(const int* __restrict__ mask) {
    int g = blockIdx.x * 256 + threadIdx.x;
    unsigned b = __ballot_sync(0xffffffffu, mask[g] != 0);
    if ((threadIdx.x & 31) == 0) g_pmask[g >> 5] = b;
}

// K: rna round + pack at position  lc*20 + ds*2 + h  <-  K[ds*8 + lc + 4h]
// (4 pad floats per lc-group of 20; row stride 80).
__global__ __launch_bounds__(256) void prep_k_kernel(const float* __restrict__ K) {
    int o = blockIdx.x * 256 + threadIdx.x;          // output element index
    int p = o % KRS;
    int row = o / KRS;
    int lcq = p / 20, q = p % 20;
    float val = 0.f;
    if (q < 16) {
        int ds = q >> 1, h = q & 1;
        val = tf32f(K[row * DIM + ds * 8 + lcq + 4 * h]);
    }
    g_Kr[o] = val;
}

// V: rna round + col permutation (vt*8+gr -> gr*8+vt) + XOR chunk swizzle.
// key(r) = ((r>>1)&1) | (((r>>2)&1)<<2)  -> rows {2lc, 2lc+1} share key
// gsw(lc) in {0,1,4,5}; every LDS.128 phase conflict-free for the AV row
// indexing (rows nt*8+2lc, nt*8+2lc+1).
__global__ __launch_bounds__(256) void prep_v_kernel(const float* __restrict__ V) {
    int o = blockIdx.x * 256 + threadIdx.x;
    int p = o & (DIM - 1);
    int row = (o >> 6);                               // global row index
    int key = ((row >> 1) & 1) | (((row >> 2) & 1) << 2);
    int chunkp = p >> 2, within = p & 3;
    int chunk = chunkp ^ key;                         // logical chunk
    int f = chunk * 4 + within;                       // logical permuted col
    int gr = f >> 3, vt = f & 7;
    int c_in = vt * 8 + gr;
    g_Vr[o] = tf32f(V[(o - p) + c_in]);
}

// ===========================================================================
// Kernel A: row sums of exp(masked scores). K-smem only -> low regs, high occ.
// R12 pipeline structure (wait_group 1, double barrier) + LDS.128 b-frags.
// ===========================================================================
__global__ __launch_bounds__(128) void rowsum_kernel(
    const float* __restrict__ Q, float* __restrict__ dummy)
{
    const int bh = blockIdx.y;
    const int q0 = blockIdx.x * QB;
    const float* Qp = Q + ((size_t)bh * SEQ + q0) * DIM;
    const float* Kp = g_Kr + (size_t)bh * SEQ * KRS;

    extern __shared__ float smemA[];
    float (*Ks)[KB][KRS] = reinterpret_cast<float (*)[KB][KRS]>(smemA);

    const int tid  = threadIdx.x;
    const int warp = tid >> 5;
    const int lane = tid & 31;
    const int gr   = lane >> 2;
    const int lc   = lane & 3;
    const int qg0  = q0 + warp * 16 + gr;
    const unsigned* pmBase = g_pmask + (size_t)qg0 * MW;

    // Stage Q into Ks[0] (plain layout, row stride KRS); hoist A fragments.
#pragma unroll
    for (int it = 0; it < 8; it++) {
        int j = tid + it * 128;
        int r = j >> 4, cc = (j & 15) << 2;
        float4 v = *reinterpret_cast<const float4*>(Qp + (size_t)r * DIM + cc);
        Ks[0][r][cc + 0] = tf32f(v.x * SCALE_L2E);
        Ks[0][r][cc + 1] = tf32f(v.y * SCALE_L2E);
        Ks[0][r][cc + 2] = tf32f(v.z * SCALE_L2E);
        Ks[0][r][cc + 3] = tf32f(v.w * SCALE_L2E);
    }
    __syncthreads();
    unsigned a[8][4];
#pragma unroll
    for (int ds = 0; ds < 8; ds++) {
        a[ds][0] = __float_as_uint(Ks[0][warp * 16 + gr    ][ds * 8 + lc    ]);
        a[ds][1] = __float_as_uint(Ks[0][warp * 16 + gr + 8][ds * 8 + lc    ]);
        a[ds][2] = __float_as_uint(Ks[0][warp * 16 + gr    ][ds * 8 + lc + 4]);
        a[ds][3] = __float_as_uint(Ks[0][warp * 16 + gr + 8][ds * 8 + lc + 4]);
    }
    __syncthreads();

    // COALESCED loader: chunk ch = it*128 + tid; adjacent lanes -> adjacent 16B.
    auto issueK = [&](int kt, int buf) {
        const float* Kt = Kp + (size_t)kt * KB * KRS;
#pragma unroll
        for (int it = 0; it < 10; it++) {
            int ch = it * 128 + tid;          // 0..1279 float4 chunks
            int r = ch / 20, c4 = ch % 20;
            cp_async16(&Ks[buf][r][c4 * 4], Kt + (size_t)r * KRS + c4 * 4);
        }
    };

    float rs0 = 0.f, rs1 = 0.f;
    issueK(0, 0); CP_COMMIT();

    for (int kt = 0; kt < NT; kt++) {
        const int cur = kt & 1;
        if (kt + 1 < NT) { issueK(kt + 1, cur ^ 1); CP_COMMIT(); }
        const unsigned* pm = pmBase + kt * 2;
        unsigned w0a = pm[0], w0b = pm[1];
        unsigned w1a = pm[8 * MW], w1b = pm[8 * MW + 1];
        if (kt + 1 < NT) asm volatile("cp.async.wait_group 1;\n");
        else             asm volatile("cp.async.wait_group 0;\n");
        __syncthreads();

        float c[8][4];
#pragma unroll
        for (int nt = 0; nt < 8; nt++) { c[nt][0]=c[nt][1]=c[nt][2]=c[nt][3]=0.f; }
#pragma unroll
        for (int j = 0; j < 4; j++) {           // ds pairs (2j, 2j+1)
#pragma unroll
            for (int nt = 0; nt < 8; nt++) {
                float4 kc = *reinterpret_cast<const float4*>(
                    &Ks[cur][nt * 8 + gr][lc * 20 + j * 4]);
                mma_tf32(c[nt], a[2*j    ], __float_as_uint(kc.x), __float_as_uint(kc.y));
                mma_tf32(c[nt], a[2*j + 1], __float_as_uint(kc.z), __float_as_uint(kc.w));
            }
        }
#pragma unroll
        for (int nt = 0; nt < 8; nt++) {
            int colb = nt * 8 + lc * 2;
            unsigned wa = (nt < 4) ? w0a : w0b;
            unsigned wb = (nt < 4) ? w1a : w1b;
            int sh = colb & 31;
            float e0 = ((wa >> sh) & 1u)       ? ex2(c[nt][0]) : 0.f;
            float e1 = ((wa >> (sh + 1)) & 1u) ? ex2(c[nt][1]) : 0.f;
            float e2 = ((wb >> sh) & 1u)       ? ex2(c[nt][2]) : 0.f;
            float e3 = ((wb >> (sh + 1)) & 1u) ? ex2(c[nt][3]) : 0.f;
            rs0 += e0 + e1;
            rs1 += e2 + e3;
        }
        __syncthreads();
    }

    rs0 += __shfl_xor_sync(0xffffffffu, rs0, 1);
    rs0 += __shfl_xor_sync(0xffffffffu, rs0, 2);
    rs1 += __shfl_xor_sync(0xffffffffu, rs1, 1);
    rs1 += __shfl_xor_sync(0xffffffffu, rs1, 2);
    if (lc == 0) {
        g_inv[bh * SEQ + qg0    ] = 1.f / rs0;
        g_inv[bh * SEQ + qg0 + 8] = 1.f / rs1;
    }
    (void)dummy;
}

// ===========================================================================
// Kernel B: recompute scores, write normalized P once, O = Pn @ V.
// R12 pipeline structure; LDS.128 b-frags; log2-fold normalization.
// ===========================================================================
__global__ __launch_bounds__(128) void av_kernel(
    const float* __restrict__ Q, float* __restrict__ P, float* __restrict__ O)
{
    const int bh = blockIdx.y;
    const int q0 = blockIdx.x * QB;
    const float* Qp = Q + ((size_t)bh * SEQ + q0) * DIM;
    const float* Kp = g_Kr + (size_t)bh * SEQ * KRS;
    const float* Vp = g_Vr + (size_t)bh * SEQ * DIM;
    float* Pp = P + ((size_t)bh * SEQ + q0) * SEQ;
    float* Op = O + ((size_t)bh * SEQ + q0) * DIM;

    extern __shared__ float smem[];
    float (*Ks)[KB][KRS] = reinterpret_cast<float (*)[KB][KRS]>(smem);
    float (*Vs)[KB][VRS] = reinterpret_cast<float (*)[KB][VRS]>(smem + 2 * KB * KRS);

    const int tid  = threadIdx.x;
    const int warp = tid >> 5;
    const int lane = tid & 31;
    const int gr   = lane >> 2;
    const int lc   = lane & 3;
    const int qg0  = q0 + warp * 16 + gr;
    const int gsw  = (lc & 1) | ((lc & 2) << 1);   // V chunk swizzle key for rows 2lc,2lc+1
    const unsigned* pmBase = g_pmask + (size_t)qg0 * MW;

    // normalization as log2-domain accumulator bias
    const float l0 = __log2f(g_inv[bh * SEQ + qg0    ]);
    const float l1 = __log2f(g_inv[bh * SEQ + qg0 + 8]);

    // Stage Q into Ks[0]; hoist A fragments.
#pragma unroll
    for (int it = 0; it < 8; it++) {
        int j = tid + it * 128;
        int r = j >> 4, cc = (j & 15) << 2;
        float4 v = *reinterpret_cast<const float4*>(Qp + (size_t)r * DIM + cc);
        Ks[0][r][cc + 0] = tf32f(v.x * SCALE_L2E);
        Ks[0][r][cc + 1] = tf32f(v.y * SCALE_L2E);
        Ks[0][r][cc + 2] = tf32f(v.z * SCALE_L2E);
        Ks[0][r][cc + 3] = tf32f(v.w * SCALE_L2E);
    }
    __syncthreads();
    unsigned a[8][4];
#pragma unroll
    for (int ds = 0; ds < 8; ds++) {
        a[ds][0] = __float_as_uint(Ks[0][warp * 16 + gr    ][ds * 8 + lc    ]);
        a[ds][1] = __float_as_uint(Ks[0][warp * 16 + gr + 8][ds * 8 + lc    ]);
        a[ds][2] = __float_as_uint(Ks[0][warp * 16 + gr    ][ds * 8 + lc + 4]);
        a[ds][3] = __float_as_uint(Ks[0][warp * 16 + gr + 8][ds * 8 + lc + 4]);
    }
    __syncthreads();

    auto issueK = [&](int kt, int buf) {
        const float* Kt = Kp + (size_t)kt * KB * KRS;
#pragma unroll
        for (int it = 0; it < 10; it++) {
            int ch = it * 128 + tid;
            int r = ch / 20, c4 = ch % 20;
            cp_async16(&Ks[buf][r][c4 * 4], Kt + (size_t)r * KRS + c4 * 4);
        }
    };
    auto issueV = [&](int kt, int buf) {
        const float* Vt = Vp + (size_t)kt * KB * DIM;
#pragma unroll
        for (int it = 0; it < 8; it++) {
            int j = tid + it * 128;
            int r = j >> 4, cc = (j & 15) << 2;
            cp_async16(&Vs[buf][r][cc], Vt + (size_t)r * DIM + cc);
        }
    };

    float acc[8][4];
#pragma unroll
    for (int vt = 0; vt < 8; vt++) { acc[vt][0]=acc[vt][1]=acc[vt][2]=acc[vt][3]=0.f; }

    issueK(0, 0); issueV(0, 0); CP_COMMIT();

    for (int kt = 0; kt < NT; kt++) {
        const int cur = kt & 1;
        if (kt + 1 < NT) { issueK(kt + 1, cur ^ 1); issueV(kt + 1, cur ^ 1); CP_COMMIT(); }
        const unsigned* pm = pmBase + kt * 2;
        unsigned w0a = pm[0], w0b = pm[1];
        unsigned w1a = pm[8 * MW], w1b = pm[8 * MW + 1];
        if (kt + 1 < NT) asm volatile("cp.async.wait_group 1;\n");
        else             asm volatile("cp.async.wait_group 0;\n");
        __syncthreads();

        float c[8][4];
#pragma unroll
        for (int nt = 0; nt < 8; nt++) {
            c[nt][0] = l0; c[nt][1] = l0; c[nt][2] = l1; c[nt][3] = l1;
        }
#pragma unroll
        for (int j = 0; j < 4; j++) {
#pragma unroll
            for (int nt = 0; nt < 8; nt++) {
                float4 kc = *reinterpret_cast<const float4*>(
                    &Ks[cur][nt * 8 + gr][lc * 20 + j * 4]);
                mma_tf32(c[nt], a[2*j    ], __float_as_uint(kc.x), __float_as_uint(kc.y));
                mma_tf32(c[nt], a[2*j + 1], __float_as_uint(kc.z), __float_as_uint(kc.w));
            }
        }

#pragma unroll
        for (int nt = 0; nt < 8; nt++) {
            int colb = nt * 8 + lc * 2;
            unsigned wa = (nt < 4) ? w0a : w0b;
            unsigned wb = (nt < 4) ? w1a : w1b;
            int sh = colb & 31;
            float p0 = ((wa >> sh) & 1u)       ? ex2(c[nt][0]) : 0.f;
            float p1 = ((wa >> (sh + 1)) & 1u) ? ex2(c[nt][1]) : 0.f;
            float p2 = ((wb >> sh) & 1u)       ? ex2(c[nt][2]) : 0.f;
            float p3 = ((wb >> (sh + 1)) & 1u) ? ex2(c[nt][3]) : 0.f;

            // final attention store (normalized, streaming hint)
            int col = kt * KB + colb;
            __stcs(reinterpret_cast<float2*>(Pp + (size_t)(warp * 16 + gr    ) * SEQ + col),
                   make_float2(p0, p1));
            __stcs(reinterpret_cast<float2*>(Pp + (size_t)(warp * 16 + gr + 8) * SEQ + col),
                   make_float2(p2, p3));

            // C-fragment IS the A-fragment under the permuted-k AV mma.
            unsigned afr[4];
            afr[0] = f2tf32(p0);
            afr[1] = f2tf32(p2);
            afr[2] = f2tf32(p1);
            afr[3] = f2tf32(p3);

            // B operand rows permuted to match: b0 = V[2lc][*], b1 = V[2lc+1][*]
            const float* vrow0 = &Vs[cur][nt * 8 + 2 * lc    ][0];
            const float* vrow1 = &Vs[cur][nt * 8 + 2 * lc + 1][0];
            float4 A0 = *reinterpret_cast<const float4*>(vrow0 + (((2*gr  ) ^ gsw) << 2));
            float4 A1 = *reinterpret_cast<const float4*>(vrow0 + (((2*gr+1) ^ gsw) << 2));
            float4 B0 = *reinterpret_cast<const float4*>(vrow1 + (((2*gr  ) ^ gsw) << 2));
            float4 B1 = *reinterpret_cast<const float4*>(vrow1 + (((2*gr+1) ^ gsw) << 2));

            mma_tf32(acc[0], afr, __float_as_uint(A0.x), __float_as_uint(B0.x));
            mma_tf32(acc[1], afr, __float_as_uint(A0.y), __float_as_uint(B0.y));
            mma_tf32(acc[2], afr, __float_as_uint(A0.z), __float_as_uint(B0.z));
            mma_tf32(acc[3], afr, __float_as_uint(A0.w), __float_as_uint(B0.w));
            mma_tf32(acc[4], afr, __float_as_uint(A1.x), __float_as_uint(B1.x));
            mma_tf32(acc[5], afr, __float_as_uint(A1.y), __float_as_uint(B1.y));
            mma_tf32(acc[6], afr, __float_as_uint(A1.z), __float_as_uint(B1.z));
            mma_tf32(acc[7], afr, __float_as_uint(A1.w), __float_as_uint(B1.w));
        }
        __syncthreads();
    }

    // Write O. acc[vt] holds output columns vt*8 + {2lc, 2lc+1} for rows gr, gr+8.
#pragma unroll
    for (int vt = 0; vt < 8; vt++) {
        int col = vt * 8 + lc * 2;
        *reinterpret_cast<float2*>(Op + (size_t)(warp * 16 + gr    ) * DIM + col) =
            make_float2(acc[vt][0], acc[vt][1]);
        *reinterpret_cast<float2*>(Op + (size_t)(warp * 16 + gr + 8) * DIM + col) =
            make_float2(acc[vt][2], acc[vt][3]);
    }
}

// ===========================================================================
extern "C" void kernel_launch(void* const* d_in, const int* in_sizes, int n_in,
                              void* d_out, int out_size) {
    (void)in_sizes; (void)n_in; (void)out_size;
    const float* Q   = (const float*)d_in[0];
    const float* K   = (const float*)d_in[1];
    const float* V   = (const float*)d_in[2];
    const int*  mask = (const int*)d_in[3];

    float* O = (float*)d_out;
    float* P = (float*)d_out + (size_t)NBH * SEQ * DIM;

    const int smemA = 2 * KB * KRS * sizeof(float);                       // 40960
    const int smemB = (2 * KB * KRS + 2 * KB * VRS) * sizeof(float);      // 73728
    cudaFuncSetAttribute(rowsum_kernel,
                         cudaFuncAttributeMaxDynamicSharedMemorySize, smemA);
    cudaFuncSetAttribute(av_kernel,
                         cudaFuncAttributeMaxDynamicSharedMemorySize, smemB);

    pack_mask_kernel<<<(SEQ * SEQ) / 256, 256>>>(mask);
    prep_k_kernel<<<(NBH * SEQ * KRS) / 256, 256>>>(K);
    prep_v_kernel<<<(NBH * SEQ * DIM) / 256, 256>>>(V);

    dim3 grid(SEQ / QB, NBH);
    rowsum_kernel<<<grid, 128, smemA>>>(Q, O);
    av_kernel<<<grid, 128, smemB>>>(Q, P, O);
}

// round 15
// speedup vs baseline: 1.5223x; 1.0592x over previous
#include <cuda_runtime.h>
#include <cstdint>

#define SEQ   4096
#define DIM   64
#define NBH   16          // B*H
#define QB    64
#define KB    64
#define NT    (SEQ/KB)    // 64 key tiles
#define MW    (SEQ/32)    // packed mask words per row
// scale * log2(e): scores computed directly in log2 domain for ex2.approx
#define SCALE_L2E 0.1803368801111204f

#define KRSA  72          // rowsum K smem row stride (floats): LDS.64 layout
#define KRSB  80          // av K row stride (floats): LDS.128 packed layout
#define VRS   64          // V smem row stride (floats): swizzled, no pad

// Scratch (allocation-free per harness rules).
__device__ unsigned g_pmask[SEQ * MW];
__device__ float g_Kr[NBH * SEQ * DIM];    // rna tf32, col-permuted (LDS.64 pairs), stride 64
__device__ float g_Kp[NBH * SEQ * KRSB];   // rna tf32, packed for LDS.128 b-frags, stride 80
__device__ float g_Vr[NBH * SEQ * DIM];    // rna tf32, col-permuted + XOR chunk swizzle
__device__ float g_inv[NBH * SEQ];         // 1 / rowsum

__device__ __forceinline__ unsigned f2tf32(float f) {
    unsigned u;
    asm("cvt.rna.tf32.f32 %0, %1;" : "=r"(u) : "f"(f));
    return u;
}
__device__ __forceinline__ float tf32f(float f) { return __uint_as_float(f2tf32(f)); }

__device__ __forceinline__ float ex2(float x) {
    float y;
    asm("ex2.approx.f32 %0, %1;" : "=f"(y) : "f"(x));
    return y;
}

__device__ __forceinline__ void mma_tf32(float c[4], const unsigned a[4],
                                         unsigned b0, unsigned b1) {
    asm volatile(
        "mma.sync.aligned.m16n8k8.row.col.f32.tf32.tf32.f32 "
        "{%0,%1,%2,%3}, {%4,%5,%6,%7}, {%8,%9}, {%0,%1,%2,%3};\n"
        : "+f"(c[0]), "+f"(c[1]), "+f"(c[2]), "+f"(c[3])
        : "r"(a[0]), "r"(a[1]), "r"(a[2]), "r"(a[3]), "r"(b0), "r"(b1));
}

__device__ __forceinline__ void cp_async16(void* dst, const void* src) {
    unsigned s = (unsigned)__cvta_generic_to_shared(dst);
    asm volatile("cp.async.cg.shared.global [%0], [%1], 16;\n" :: "r"(s), "l"(src));
}
#define CP_COMMIT() asm volatile("cp.async.commit_group;\n")

// ===========================================================================
// Prep kernels
// ===========================================================================
__global__ __launch_bounds__(256) void pack_mask_kernel(const int* __restrict__ mask) {
    int g = blockIdx.x * 256 + threadIdx.x;
    unsigned b = __ballot_sync(0xffffffffu, mask[g] != 0);
    if ((threadIdx.x & 31) == 0) g_pmask[g >> 5] = b;
}

// K layout A (rowsum): rna round + column permutation
//   p = ds*8 + 2*lc + h  <-  c_in = ds*8 + lc + 4*h   (row stride 64)
__global__ __launch_bounds__(256) void prep_ka_kernel(const float* __restrict__ K) {
    int o = blockIdx.x * 256 + threadIdx.x;          // output element index
    int p = o & (DIM - 1);
    int rowbase = o - p;
    int ds = p >> 3, t = p & 7;
    int lc = t >> 1, h = t & 1;
    int c_in = ds * 8 + lc + 4 * h;
    g_Kr[o] = tf32f(K[rowbase + c_in]);
}

// K layout B (av): rna round + pack at position lc*20 + ds*2 + h
//   <- K[ds*8 + lc + 4h]   (4 pad floats per lc-group of 20; row stride 80)
__global__ __launch_bounds__(256) void prep_kb_kernel(const float* __restrict__ K) {
    int o = blockIdx.x * 256 + threadIdx.x;          // output element index
    int p = o % KRSB;
    int row = o / KRSB;
    int lcq = p / 20, q = p % 20;
    float val = 0.f;
    if (q < 16) {
        int ds = q >> 1, h = q & 1;
        val = tf32f(K[row * DIM + ds * 8 + lcq + 4 * h]);
    }
    g_Kp[o] = val;
}

// V: rna round + col permutation (vt*8+gr -> gr*8+vt) + XOR chunk swizzle.
// key(r) = ((r>>1)&1) | (((r>>2)&1)<<2)  -> rows {2lc, 2lc+1} share key
// gsw(lc) in {0,1,4,5}; every LDS.128 phase conflict-free for the AV row
// indexing (rows nt*8+2lc, nt*8+2lc+1).
__global__ __launch_bounds__(256) void prep_v_kernel(const float* __restrict__ V) {
    int o = blockIdx.x * 256 + threadIdx.x;
    int p = o & (DIM - 1);
    int row = (o >> 6);                               // global row index
    int key = ((row >> 1) & 1) | (((row >> 2) & 1) << 2);
    int chunkp = p >> 2, within = p & 3;
    int chunk = chunkp ^ key;                         // logical chunk
    int f = chunk * 4 + within;                       // logical permuted col
    int gr = f >> 3, vt = f & 7;
    int c_in = vt * 8 + gr;
    g_Vr[o] = tf32f(V[(o - p) + c_in]);
}

// ===========================================================================
// Kernel A: row sums of exp(masked scores). Exact R12 version (best measured:
// 247us, 96 regs, occ 24.9%). K layout A (stride-64 global, stride-72 smem).
// ===========================================================================
__global__ __launch_bounds__(128) void rowsum_kernel(
    const float* __restrict__ Q, float* __restrict__ dummy)
{
    const int bh = blockIdx.y;
    const int q0 = blockIdx.x * QB;
    const float* Qp = Q + ((size_t)bh * SEQ + q0) * DIM;
    const float* Kp = g_Kr + (size_t)bh * SEQ * DIM;

    extern __shared__ float smemA[];
    float (*Ks)[KB][KRSA] = reinterpret_cast<float (*)[KB][KRSA]>(smemA);

    const int tid  = threadIdx.x;
    const int warp = tid >> 5;
    const int lane = tid & 31;
    const int gr   = lane >> 2;
    const int lc   = lane & 3;
    const int qg0  = q0 + warp * 16 + gr;
    const unsigned* pmBase = g_pmask + (size_t)qg0 * MW;

    // Stage Q into Ks[0]; hoist A fragments.
#pragma unroll
    for (int it = 0; it < 8; it++) {
        int j = tid + it * 128;
        int r = j >> 4, cc = (j & 15) << 2;
        float4 v = *reinterpret_cast<const float4*>(Qp + (size_t)r * DIM + cc);
        Ks[0][r][cc + 0] = tf32f(v.x * SCALE_L2E);
        Ks[0][r][cc + 1] = tf32f(v.y * SCALE_L2E);
        Ks[0][r][cc + 2] = tf32f(v.z * SCALE_L2E);
        Ks[0][r][cc + 3] = tf32f(v.w * SCALE_L2E);
    }
    __syncthreads();
    unsigned a[8][4];
#pragma unroll
    for (int ds = 0; ds < 8; ds++) {
        a[ds][0] = __float_as_uint(Ks[0][warp * 16 + gr    ][ds * 8 + lc    ]);
        a[ds][1] = __float_as_uint(Ks[0][warp * 16 + gr + 8][ds * 8 + lc    ]);
        a[ds][2] = __float_as_uint(Ks[0][warp * 16 + gr    ][ds * 8 + lc + 4]);
        a[ds][3] = __float_as_uint(Ks[0][warp * 16 + gr + 8][ds * 8 + lc + 4]);
    }
    __syncthreads();

    auto issueK = [&](int kt, int buf) {
        const float* Kt = Kp + (size_t)kt * KB * DIM;
#pragma unroll
        for (int it = 0; it < 8; it++) {
            int j = tid + it * 128;
            int r = j >> 4, cc = (j & 15) << 2;
            cp_async16(&Ks[buf][r][cc], Kt + (size_t)r * DIM + cc);
        }
    };

    float rs0 = 0.f, rs1 = 0.f;
    issueK(0, 0); CP_COMMIT();

    for (int kt = 0; kt < NT; kt++) {
        const int cur = kt & 1;
        if (kt + 1 < NT) { issueK(kt + 1, cur ^ 1); CP_COMMIT(); }
        const unsigned* pm = pmBase + kt * 2;
        unsigned w0a = pm[0], w0b = pm[1];
        unsigned w1a = pm[8 * MW], w1b = pm[8 * MW + 1];
        if (kt + 1 < NT) asm volatile("cp.async.wait_group 1;\n");
        else             asm volatile("cp.async.wait_group 0;\n");
        __syncthreads();

        float c[8][4];
#pragma unroll
        for (int nt = 0; nt < 8; nt++) { c[nt][0]=c[nt][1]=c[nt][2]=c[nt][3]=0.f; }
#pragma unroll
        for (int ds = 0; ds < 8; ds++) {
#pragma unroll
            for (int nt = 0; nt < 8; nt++) {
                float2 kv = *reinterpret_cast<const float2*>(
                    &Ks[cur][nt * 8 + gr][ds * 8 + 2 * lc]);
                mma_tf32(c[nt], a[ds], __float_as_uint(kv.x), __float_as_uint(kv.y));
            }
        }
#pragma unroll
        for (int nt = 0; nt < 8; nt++) {
            int colb = nt * 8 + lc * 2;
            unsigned wa = (nt < 4) ? w0a : w0b;
            unsigned wb = (nt < 4) ? w1a : w1b;
            int sh = colb & 31;
            float e0 = ((wa >> sh) & 1u)       ? ex2(c[nt][0]) : 0.f;
            float e1 = ((wa >> (sh + 1)) & 1u) ? ex2(c[nt][1]) : 0.f;
            float e2 = ((wb >> sh) & 1u)       ? ex2(c[nt][2]) : 0.f;
            float e3 = ((wb >> (sh + 1)) & 1u) ? ex2(c[nt][3]) : 0.f;
            rs0 += e0 + e1;
            rs1 += e2 + e3;
        }
        __syncthreads();
    }

    rs0 += __shfl_xor_sync(0xffffffffu, rs0, 1);
    rs0 += __shfl_xor_sync(0xffffffffu, rs0, 2);
    rs1 += __shfl_xor_sync(0xffffffffu, rs1, 1);
    rs1 += __shfl_xor_sync(0xffffffffu, rs1, 2);
    if (lc == 0) {
        g_inv[bh * SEQ + qg0    ] = 1.f / rs0;
        g_inv[bh * SEQ + qg0 + 8] = 1.f / rs1;
    }
    (void)dummy;
}

// ===========================================================================
// Kernel B: recompute scores, write normalized P once, O = Pn @ V.
// Exact R14 version (best measured ~568us): K layout B (LDS.128 b-frags),
// log2-fold normalization, shuffle-free permuted-k AV epilogue.
// ===========================================================================
__global__ __launch_bounds__(128) void av_kernel(
    const float* __restrict__ Q, float* __restrict__ P, float* __restrict__ O)
{
    const int bh = blockIdx.y;
    const int q0 = blockIdx.x * QB;
    const float* Qp = Q + ((size_t)bh * SEQ + q0) * DIM;
    const float* Kp = g_Kp + (size_t)bh * SEQ * KRSB;
    const float* Vp = g_Vr + (size_t)bh * SEQ * DIM;
    float* Pp = P + ((size_t)bh * SEQ + q0) * SEQ;
    float* Op = O + ((size_t)bh * SEQ + q0) * DIM;

    extern __shared__ float smem[];
    float (*Ks)[KB][KRSB] = reinterpret_cast<float (*)[KB][KRSB]>(smem);
    float (*Vs)[KB][VRS] = reinterpret_cast<float (*)[KB][VRS]>(smem + 2 * KB * KRSB);

    const int tid  = threadIdx.x;
    const int warp = tid >> 5;
    const int lane = tid & 31;
    const int gr   = lane >> 2;
    const int lc   = lane & 3;
    const int qg0  = q0 + warp * 16 + gr;
    const int gsw  = (lc & 1) | ((lc & 2) << 1);   // V chunk swizzle key for rows 2lc,2lc+1
    const unsigned* pmBase = g_pmask + (size_t)qg0 * MW;

    // normalization as log2-domain accumulator bias
    const float l0 = __log2f(g_inv[bh * SEQ + qg0    ]);
    const float l1 = __log2f(g_inv[bh * SEQ + qg0 + 8]);

    // Stage Q into Ks[0]; hoist A fragments.
#pragma unroll
    for (int it = 0; it < 8; it++) {
        int j = tid + it * 128;
        int r = j >> 4, cc = (j & 15) << 2;
        float4 v = *reinterpret_cast<const float4*>(Qp + (size_t)r * DIM + cc);
        Ks[0][r][cc + 0] = tf32f(v.x * SCALE_L2E);
        Ks[0][r][cc + 1] = tf32f(v.y * SCALE_L2E);
        Ks[0][r][cc + 2] = tf32f(v.z * SCALE_L2E);
        Ks[0][r][cc + 3] = tf32f(v.w * SCALE_L2E);
    }
    __syncthreads();
    unsigned a[8][4];
#pragma unroll
    for (int ds = 0; ds < 8; ds++) {
        a[ds][0] = __float_as_uint(Ks[0][warp * 16 + gr    ][ds * 8 + lc    ]);
        a[ds][1] = __float_as_uint(Ks[0][warp * 16 + gr + 8][ds * 8 + lc    ]);
        a[ds][2] = __float_as_uint(Ks[0][warp * 16 + gr    ][ds * 8 + lc + 4]);
        a[ds][3] = __float_as_uint(Ks[0][warp * 16 + gr + 8][ds * 8 + lc + 4]);
    }
    __syncthreads();

    auto issueK = [&](int kt, int buf) {
        const float* Kt = Kp + (size_t)kt * KB * KRSB;
#pragma unroll
        for (int it = 0; it < 10; it++) {
            int ch = it * 128 + tid;
            int r = ch / 20, c4 = ch % 20;
            cp_async16(&Ks[buf][r][c4 * 4], Kt + (size_t)r * KRSB + c4 * 4);
        }
    };
    auto issueV = [&](int kt, int buf) {
        const float* Vt = Vp + (size_t)kt * KB * DIM;
#pragma unroll
        for (int it = 0; it < 8; it++) {
            int j = tid + it * 128;
            int r = j >> 4, cc = (j & 15) << 2;
            cp_async16(&Vs[buf][r][cc], Vt + (size_t)r * DIM + cc);
        }
    };

    float acc[8][4];
#pragma unroll
    for (int vt = 0; vt < 8; vt++) { acc[vt][0]=acc[vt][1]=acc[vt][2]=acc[vt][3]=0.f; }

    issueK(0, 0); issueV(0, 0); CP_COMMIT();

    for (int kt = 0; kt < NT; kt++) {
        const int cur = kt & 1;
        if (kt + 1 < NT) { issueK(kt + 1, cur ^ 1); issueV(kt + 1, cur ^ 1); CP_COMMIT(); }
        const unsigned* pm = pmBase + kt * 2;
        unsigned w0a = pm[0], w0b = pm[1];
        unsigned w1a = pm[8 * MW], w1b = pm[8 * MW + 1];
        if (kt + 1 < NT) asm volatile("cp.async.wait_group 1;\n");
        else             asm volatile("cp.async.wait_group 0;\n");
        __syncthreads();

        float c[8][4];
#pragma unroll
        for (int nt = 0; nt < 8; nt++) {
            c[nt][0] = l0; c[nt][1] = l0; c[nt][2] = l1; c[nt][3] = l1;
        }
#pragma unroll
        for (int j = 0; j < 4; j++) {
#pragma unroll
            for (int nt = 0; nt < 8; nt++) {
                float4 kc = *reinterpret_cast<const float4*>(
                    &Ks[cur][nt * 8 + gr][lc * 20 + j * 4]);
                mma_tf32(c[nt], a[2*j    ], __float_as_uint(kc.x), __float_as_uint(kc.y));
                mma_tf32(c[nt], a[2*j + 1], __float_as_uint(kc.z), __float_as_uint(kc.w));
            }
        }

#pragma unroll
        for (int nt = 0; nt < 8; nt++) {
            int colb = nt * 8 + lc * 2;
            unsigned wa = (nt < 4) ? w0a : w0b;
            unsigned wb = (nt < 4) ? w1a : w1b;
            int sh = colb & 31;
            float p0 = ((wa >> sh) & 1u)       ? ex2(c[nt][0]) : 0.f;
            float p1 = ((wa >> (sh + 1)) & 1u) ? ex2(c[nt][1]) : 0.f;
            float p2 = ((wb >> sh) & 1u)       ? ex2(c[nt][2]) : 0.f;
            float p3 = ((wb >> (sh + 1)) & 1u) ? ex2(c[nt][3]) : 0.f;

            // final attention store (normalized, streaming hint)
            int col = kt * KB + colb;
            __stcs(reinterpret_cast<float2*>(Pp + (size_t)(warp * 16 + gr    ) * SEQ + col),
                   make_float2(p0, p1));
            __stcs(reinterpret_cast<float2*>(Pp + (size_t)(warp * 16 + gr + 8) * SEQ + col),
                   make_float2(p2, p3));

            // C-fragment IS the A-fragment under the permuted-k AV mma.
            unsigned afr[4];
            afr[0] = f2tf32(p0);
            afr[1] = f2tf32(p2);
            afr[2] = f2tf32(p1);
            afr[3] = f2tf32(p3);

            // B operand rows permuted to match: b0 = V[2lc][*], b1 = V[2lc+1][*]
            const float* vrow0 = &Vs[cur][nt * 8 + 2 * lc    ][0];
            const float* vrow1 = &Vs[cur][nt * 8 + 2 * lc + 1][0];
            float4 A0 = *reinterpret_cast<const float4*>(vrow0 + (((2*gr  ) ^ gsw) << 2));
            float4 A1 = *reinterpret_cast<const float4*>(vrow0 + (((2*gr+1) ^ gsw) << 2));
            float4 B0 = *reinterpret_cast<const float4*>(vrow1 + (((2*gr  ) ^ gsw) << 2));
            float4 B1 = *reinterpret_cast<const float4*>(vrow1 + (((2*gr+1) ^ gsw) << 2));

            mma_tf32(acc[0], afr, __float_as_uint(A0.x), __float_as_uint(B0.x));
            mma_tf32(acc[1], afr, __float_as_uint(A0.y), __float_as_uint(B0.y));
            mma_tf32(acc[2], afr, __float_as_uint(A0.z), __float_as_uint(B0.z));
            mma_tf32(acc[3], afr, __float_as_uint(A0.w), __float_as_uint(B0.w));
            mma_tf32(acc[4], afr, __float_as_uint(A1.x), __float_as_uint(B1.x));
            mma_tf32(acc[5], afr, __float_as_uint(A1.y), __float_as_uint(B1.y));
            mma_tf32(acc[6], afr, __float_as_uint(A1.z), __float_as_uint(B1.z));
            mma_tf32(acc[7], afr, __float_as_uint(A1.w), __float_as_uint(B1.w));
        }
        __syncthreads();
    }

    // Write O. acc[vt] holds output columns vt*8 + {2lc, 2lc+1} for rows gr, gr+8.
#pragma unroll
    for (int vt = 0; vt < 8; vt++) {
        int col = vt * 8 + lc * 2;
        *reinterpret_cast<float2*>(Op + (size_t)(warp * 16 + gr    ) * DIM + col) =
            make_float2(acc[vt][0], acc[vt][1]);
        *reinterpret_cast<float2*>(Op + (size_t)(warp * 16 + gr + 8) * DIM + col) =
            make_float2(acc[vt][2], acc[vt][3]);
    }
}

// ===========================================================================
extern "C" void kernel_launch(void* const* d_in, const int* in_sizes, int n_in,
                              void* d_out, int out_size) {
    (void)in_sizes; (void)n_in; (void)out_size;
    const float* Q   = (const float*)d_in[0];
    const float* K   = (const float*)d_in[1];
    const float* V   = (const float*)d_in[2];
    const int*  mask = (const int*)d_in[3];

    float* O = (float*)d_out;
    float* P = (float*)d_out + (size_t)NBH * SEQ * DIM;

    const int smemA = 2 * KB * KRSA * sizeof(float);                      // 36864
    const int smemB = (2 * KB * KRSB + 2 * KB * VRS) * sizeof(float);     // 73728
    cudaFuncSetAttribute(rowsum_kernel,
                         cudaFuncAttributeMaxDynamicSharedMemorySize, smemA);
    cudaFuncSetAttribute(av_kernel,
                         cudaFuncAttributeMaxDynamicSharedMemorySize, smemB);

    pack_mask_kernel<<<(SEQ * SEQ) / 256, 256>>>(mask);
    prep_ka_kernel<<<(NBH * SEQ * DIM) / 256, 256>>>(K);
    prep_kb_kernel<<<(NBH * SEQ * KRSB) / 256, 256>>>(K);
    prep_v_kernel<<<(NBH * SEQ * DIM) / 256, 256>>>(V);

    dim3 grid(SEQ / QB, NBH);
    rowsum_kernel<<<grid, 128, smemA>>>(Q, O);
    av_kernel<<<grid, 128, smemB>>>(Q, P, O);
}